// round 9
// baseline (speedup 1.0000x reference)
#include <cuda_runtime.h>
#include <cuda_fp16.h>
#include <math.h>
#include <stdint.h>

// ===========================================================================
// COR_Critic — single-pass fp16 HMMA pipeline; fused tail.
//   G0:  X1 = tanh(sa @ A1 + b1)*gate1          [B,1024]   (mma_gemm)
//   G1:  X2 = tanh(X1 @ A2 + b2)*gate2          [B,1024]   (mma_gemm, dominant)
//   FUSED per 64-row block:
//     H1p = X2 @ Wq1 + bq1        (HMMA, K=1024, N=256, acc fp32)
//     H1  = relu(LN(H1p))         (in SMEM, re-swizzled fp16)
//     H2p = H1 @ Wq2 + bq2        (HMMA from SMEM, K=256, N=128)
//     out = relu(LN(H2p)) @ Wq3 + bq3
// ===========================================================================

#define NB 131072
using fp16 = __half;

__device__ fp16 g_SAf[(size_t)NB * 64];
__device__ fp16 g_W1t[1024 * 64];
__device__ fp16 g_W2t[1024 * 1024];
__device__ fp16 g_Q1t[256 * 1024];
__device__ fp16 g_Q2t[128 * 256];
__device__ fp16 g_X1f[(size_t)NB * 1024];
__device__ fp16 g_X2f[(size_t)NB * 1024];
__device__ float g_GATE[64];

// ---------------- PTX helpers ----------------------------------------------
__device__ __forceinline__ uint32_t smem_u32(const void* p) {
    uint32_t a;
    asm("{ .reg .u64 t; cvta.to.shared.u64 t, %1; cvt.u32.u64 %0, t; }"
        : "=r"(a) : "l"(p));
    return a;
}
__device__ __forceinline__ void cp16(uint32_t s, const void* g) {
    asm volatile("cp.async.cg.shared.global [%0], [%1], 16;" :: "r"(s), "l"(g));
}
#define CP_COMMIT() asm volatile("cp.async.commit_group;" ::: "memory")
__device__ __forceinline__ void ldsm4(uint32_t* r, uint32_t a) {
    asm volatile("ldmatrix.sync.aligned.m8n8.x4.shared.b16 {%0,%1,%2,%3}, [%4];"
                 : "=r"(r[0]), "=r"(r[1]), "=r"(r[2]), "=r"(r[3]) : "r"(a));
}
__device__ __forceinline__ void ldsm2(uint32_t* r, uint32_t a) {
    asm volatile("ldmatrix.sync.aligned.m8n8.x2.shared.b16 {%0,%1}, [%2];"
                 : "=r"(r[0]), "=r"(r[1]) : "r"(a));
}
__device__ __forceinline__ void mma16816(float* d, const uint32_t* a, const uint32_t* b) {
    asm volatile(
        "mma.sync.aligned.m16n8k16.row.col.f32.f16.f16.f32 "
        "{%0,%1,%2,%3}, {%4,%5,%6,%7}, {%8,%9}, {%0,%1,%2,%3};"
        : "+f"(d[0]), "+f"(d[1]), "+f"(d[2]), "+f"(d[3])
        : "r"(a[0]), "r"(a[1]), "r"(a[2]), "r"(a[3]), "r"(b[0]), "r"(b[1]));
}

// ---------------- prep kernels ---------------------------------------------
__global__ void prep_saf(const float* __restrict__ st, const float* __restrict__ ac,
                         fp16* __restrict__ o, int M) {
    int idx = blockIdx.x * blockDim.x + threadIdx.x;
    if (idx >= M * 64) return;
    int b = idx >> 6, j = idx & 63;
    float v = 0.f;
    if (j < 24) v = st[b * 24 + j];
    else if (j < 32) v = ac[b * 8 + (j - 24)];
    o[idx] = __float2half_rn(v);
}
__global__ void prep_w1t(const float* __restrict__ W, fp16* __restrict__ h) {
    int idx = blockIdx.x * blockDim.x + threadIdx.x;
    if (idx >= 1024 * 64) return;
    int n = idx >> 6, k = idx & 63;
    float v = (k < 32) ? W[((size_t)((n >> 5) * 32 + k)) * 32 + (n & 31)] : 0.f;
    h[idx] = __float2half_rn(v);
}
__global__ void prep_w2t(const float* __restrict__ W, fp16* __restrict__ h) {
    int idx = blockIdx.x * blockDim.x + threadIdx.x;
    if (idx >= 1024 * 1024) return;
    int n = idx >> 10, k = idx & 1023;
    h[idx] = __float2half_rn(W[((size_t)(n >> 5) * 1024 + k) * 32 + (n & 31)]);
}
__global__ void prep_wt(const float* __restrict__ W, fp16* __restrict__ h, int Nn, int K) {
    int idx = blockIdx.x * blockDim.x + threadIdx.x;
    if (idx >= Nn * K) return;
    int n = idx / K, k = idx - n * K;
    h[idx] = __float2half_rn(W[(size_t)k * Nn + n]);
}
__global__ void prep_gates(const float* __restrict__ g1, const float* __restrict__ g2,
                           float* __restrict__ out) {
    int t = threadIdx.x;
    if (t < 32)      out[t] = 1.0f / (1.0f + expf(-g1[t]));
    else if (t < 64) out[t] = 1.0f / (1.0f + expf(-g2[t - 32]));
}

// ---------------- HMMA GEMM (ripple layers) ---------------------------------
// C[M,N] = Af[M,K] @ W[N,K]^T; BM=128, BN=128, BK=64, 8 warps (4m x 2n).
// epilogue: tanh(acc+bias)*gate -> fp16.
__global__ void __launch_bounds__(256)
mma_gemm(const fp16* __restrict__ Af, const fp16* __restrict__ Bw,
         int K, int ldC,
         const float* __restrict__ bias, const float* __restrict__ gate,
         fp16* __restrict__ Ch) {
    constexpr int TILE = 128 * 64 * 2;
    constexpr int BUF = 2 * TILE;

    extern __shared__ char dsm[];
    const uint32_t sb = (smem_u32(dsm) + 1023) & ~1023u;

    const int tid = threadIdx.x;
    const int wid = tid >> 5, lane = tid & 31;
    const int wm = wid >> 1, wn = wid & 1;
    const size_t bm = (size_t)blockIdx.y * 128;
    const int bn = blockIdx.x * 128;
    const int nk = K >> 6;

    auto load_tile = [&](int kt, int buf) {
        const uint32_t base = sb + buf * BUF;
#pragma unroll
        for (int i = 0; i < 4; i++) {
            const int c = tid + 256 * i;
            const int row = c >> 3;
            const uint32_t sw = (uint32_t)(row * 128) +
                                (uint32_t)(((c & 7) << 4) ^ ((row & 7) << 4));
            const size_t kofs = (size_t)kt * 64 + ((c & 7) << 3);
            cp16(base + sw, Af + (bm + row) * (size_t)K + kofs);
            cp16(base + TILE + sw, Bw + (size_t)(bn + row) * K + kofs);
        }
    };

    const int r15 = lane & 15, halfA = lane >> 4;
    int pA[2], xA[2];
#pragma unroll
    for (int mt = 0; mt < 2; mt++) {
        const int rowA = wm * 32 + mt * 16 + r15;
        pA[mt] = rowA * 128;
        xA[mt] = (rowA & 7) << 4;
    }
    const int l8 = lane & 7, halfB = (lane & 15) >> 3;
    const int xB = l8 << 4;
    int pB[8];
#pragma unroll
    for (int nt = 0; nt < 8; nt++) pB[nt] = (wn * 64 + nt * 8 + l8) * 128;

    float acc[2][8][4];
#pragma unroll
    for (int mt = 0; mt < 2; mt++)
#pragma unroll
        for (int nt = 0; nt < 8; nt++)
#pragma unroll
            for (int q = 0; q < 4; q++) acc[mt][nt][q] = 0.f;

    load_tile(0, 0);
    CP_COMMIT();

    for (int kt = 0; kt < nk; kt++) {
        const int buf = kt & 1;
        if (kt + 1 < nk) {
            load_tile(kt + 1, buf ^ 1);
            CP_COMMIT();
            asm volatile("cp.async.wait_group 1;" ::: "memory");
        } else {
            asm volatile("cp.async.wait_group 0;" ::: "memory");
        }
        __syncthreads();

        const uint32_t tA = sb + buf * BUF;
        const uint32_t tB = tA + TILE;
#pragma unroll
        for (int ks = 0; ks < 4; ks++) {
            const int kbA = ks * 32 + 16 * halfA;
            const int kbB = ks * 32 + 16 * halfB;
            uint32_t a[2][4], bfr[8][2];
#pragma unroll
            for (int mt = 0; mt < 2; mt++)
                ldsm4(a[mt], tA + pA[mt] + (kbA ^ xA[mt]));
#pragma unroll
            for (int nt = 0; nt < 8; nt++)
                ldsm2(bfr[nt], tB + pB[nt] + (kbB ^ xB));
#pragma unroll
            for (int mt = 0; mt < 2; mt++)
#pragma unroll
                for (int nt = 0; nt < 8; nt++)
                    mma16816(acc[mt][nt], a[mt], bfr[nt]);
        }
        __syncthreads();
    }

    const int gid = lane >> 2, qd = lane & 3;
#pragma unroll
    for (int nt = 0; nt < 8; nt++) {
        const int c = bn + wn * 64 + nt * 8 + qd * 2;
        const float b0 = bias[c], b1 = bias[c + 1];
        const float gv = gate[c >> 5];
#pragma unroll
        for (int mt = 0; mt < 2; mt++) {
            const size_t r0 = bm + wm * 32 + mt * 16 + gid;
#pragma unroll
            for (int half = 0; half < 2; half++) {
                const size_t row = r0 + 8 * half;
                const float v0 = tanhf(acc[mt][nt][2 * half + 0] + b0) * gv;
                const float v1 = tanhf(acc[mt][nt][2 * half + 1] + b1) * gv;
                *(uint32_t*)(Ch + row * (size_t)ldC + c) =
                    ((uint32_t)__half_as_ushort(__float2half_rn(v1)) << 16) |
                    __half_as_ushort(__float2half_rn(v0));
            }
        }
    }
}

// ---------------- fused tail: G2 + LN1 + G3 + LN2 + dot ---------------------
// Per CTA: 64 rows.  8 warps as 2m x 4n.
// SMEM: [0, 81920)            2x (A 8K | B 32K) G2 tiles; later H1pre/H2pre
//       [81920, 147456)       Q2 weights 4x[128x64] swizzled fp16 (prefetch)
//       [147456, 180224)      H1 fp16 4x[64x64] swizzled (G3 A operand)
__global__ void __launch_bounds__(256)
fused_tail(const fp16* __restrict__ X2, const fp16* __restrict__ Q1,
           const fp16* __restrict__ Q2,
           const float* __restrict__ bq1, const float* __restrict__ ln1g,
           const float* __restrict__ ln1b,
           const float* __restrict__ bq2, const float* __restrict__ ln2g,
           const float* __restrict__ ln2b,
           const float* __restrict__ wq3, const float* __restrict__ bq3,
           float* __restrict__ out) {
    constexpr int TA = 64 * 128;        // 8 KB
    constexpr int STAGE = TA + 256 * 128;  // 40 KB
    constexpr int Q2OFF = 2 * STAGE;       // 81920
    constexpr int H1OFF = Q2OFF + 65536;   // 147456
    constexpr int PRE1_STRIDE = 1040;      // 256 fp32 padded (bank-safe)
    constexpr int PRE2_STRIDE = 528;       // 128 fp32 padded

    extern __shared__ char dsm[];
    const uint32_t sb = (smem_u32(dsm) + 1023) & ~1023u;

    const int tid = threadIdx.x;
    const int wid = tid >> 5, lane = tid & 31;
    const int wm = wid >> 2, wn = wid & 3;      // 2m x 4n
    const size_t bm = (size_t)blockIdx.x * 64;

    // --- prefetch Q2 (group 0) ---
#pragma unroll
    for (int i = 0; i < 16; i++) {
        const int c = tid + 256 * i;            // 0..4095
        const int ch = c >> 10;
        const int r = (c >> 3) & 127;
        const int g = c & 7;
        const uint32_t sw = (uint32_t)(r * 128) + (uint32_t)((g << 4) ^ ((r & 7) << 4));
        cp16(sb + Q2OFF + ch * 16384 + sw, Q2 + (size_t)r * 256 + ch * 64 + g * 8);
    }
    CP_COMMIT();

    auto load_tile = [&](int kt, int buf) {
        const uint32_t base = sb + buf * STAGE;
        const size_t k0 = (size_t)kt * 64;
#pragma unroll
        for (int i = 0; i < 2; i++) {           // A: 64x64
            const int c = tid + 256 * i;
            const int row = c >> 3;
            const uint32_t sw = (uint32_t)(row * 128) +
                                (uint32_t)(((c & 7) << 4) ^ ((row & 7) << 4));
            cp16(base + sw, X2 + (bm + row) * 1024 + k0 + ((c & 7) << 3));
        }
#pragma unroll
        for (int i = 0; i < 8; i++) {           // B: 256x64
            const int c = tid + 256 * i;
            const int row = c >> 3;
            const uint32_t sw = (uint32_t)(row * 128) +
                                (uint32_t)(((c & 7) << 4) ^ ((row & 7) << 4));
            cp16(base + TA + sw, Q1 + (size_t)row * 1024 + k0 + ((c & 7) << 3));
        }
    };

    const int r15 = lane & 15, halfA = lane >> 4;
    int pA[2], xA[2];
#pragma unroll
    for (int mt = 0; mt < 2; mt++) {
        const int rowA = wm * 32 + mt * 16 + r15;
        pA[mt] = rowA * 128;
        xA[mt] = (rowA & 7) << 4;
    }
    const int l8 = lane & 7, halfB = (lane & 15) >> 3;
    const int xB = l8 << 4;

    float acc[2][8][4];
#pragma unroll
    for (int mt = 0; mt < 2; mt++)
#pragma unroll
        for (int nt = 0; nt < 8; nt++)
#pragma unroll
            for (int q = 0; q < 4; q++) acc[mt][nt][q] = 0.f;

    load_tile(0, 0);
    CP_COMMIT();

    // --- G2 mainloop: K=1024, nk=16 ---
    for (int kt = 0; kt < 16; kt++) {
        const int buf = kt & 1;
        if (kt + 1 < 16) {
            load_tile(kt + 1, buf ^ 1);
            CP_COMMIT();
            asm volatile("cp.async.wait_group 1;" ::: "memory");
        } else {
            asm volatile("cp.async.wait_group 0;" ::: "memory");
        }
        __syncthreads();

        const uint32_t tA = sb + buf * STAGE;
        const uint32_t tB = tA + TA;
#pragma unroll
        for (int ks = 0; ks < 4; ks++) {
            const int kbA = ks * 32 + 16 * halfA;
            const int kbB = ks * 32 + 16 * halfB;
            uint32_t a[2][4], bfr[8][2];
#pragma unroll
            for (int mt = 0; mt < 2; mt++)
                ldsm4(a[mt], tA + pA[mt] + (kbA ^ xA[mt]));
#pragma unroll
            for (int nt = 0; nt < 8; nt++)
                ldsm2(bfr[nt], tB + (wn * 64 + nt * 8 + l8) * 128 + (kbB ^ xB));
#pragma unroll
            for (int mt = 0; mt < 2; mt++)
#pragma unroll
                for (int nt = 0; nt < 8; nt++)
                    mma16816(acc[mt][nt], a[mt], bfr[nt]);
        }
        __syncthreads();
    }

    // --- G2 epilogue: +bq1 -> H1pre fp32 in SMEM [0, 66.5K) ---
    const int gid = lane >> 2, qd = lane & 3;
#pragma unroll
    for (int nt = 0; nt < 8; nt++) {
        const int c = wn * 64 + nt * 8 + qd * 2;
        const float b0 = bq1[c], b1 = bq1[c + 1];
#pragma unroll
        for (int mt = 0; mt < 2; mt++) {
            const int r0 = wm * 32 + mt * 16 + gid;
#pragma unroll
            for (int half = 0; half < 2; half++) {
                const int row = r0 + 8 * half;
                float2 o;
                o.x = acc[mt][nt][2 * half + 0] + b0;
                o.y = acc[mt][nt][2 * half + 1] + b1;
                *(float2*)(dsm + (sb - smem_u32(dsm)) + row * PRE1_STRIDE + c * 4) = o;
            }
        }
    }
    __syncthreads();

    char* const sm = dsm + (sb - smem_u32(dsm));   // aligned smem base (generic)

    // --- LN1 + ReLU -> H1 fp16 swizzled [H1OFF, +32K) ---
    {
#pragma unroll
        for (int j = 0; j < 8; j++) {
            const int row = wid * 8 + j;
            float v[8];
            float s = 0.f;
#pragma unroll
            for (int i = 0; i < 8; i++) {
                v[i] = *(const float*)(sm + row * PRE1_STRIDE + (lane + 32 * i) * 4);
                s += v[i];
            }
#pragma unroll
            for (int o = 16; o; o >>= 1) s += __shfl_xor_sync(0xffffffffu, s, o);
            const float mu = s * (1.0f / 256.0f);
            float vs = 0.f;
#pragma unroll
            for (int i = 0; i < 8; i++) { float d = v[i] - mu; vs += d * d; }
#pragma unroll
            for (int o = 16; o; o >>= 1) vs += __shfl_xor_sync(0xffffffffu, vs, o);
            const float inv = rsqrtf(vs * (1.0f / 256.0f) + 1e-5f);
#pragma unroll
            for (int i = 0; i < 8; i++) {
                const int c = lane + 32 * i;
                float y = (v[i] - mu) * inv * ln1g[c] + ln1b[c];
                y = fmaxf(y, 0.f);
                const int k2 = (c & 63) * 2;
                const uint32_t ad = H1OFF + (c >> 6) * 8192 + row * 128 +
                                    ((k2 & 0x70) ^ ((row & 7) << 4)) + (k2 & 15);
                *(fp16*)(sm + ad) = __float2half_rn(y);
            }
        }
    }
    __syncthreads();

    // --- G3: H1[64,256] @ Q2[128,256]^T -> acc2 ---
    float acc2[2][4][4];
#pragma unroll
    for (int mt = 0; mt < 2; mt++)
#pragma unroll
        for (int nt = 0; nt < 4; nt++)
#pragma unroll
            for (int q = 0; q < 4; q++) acc2[mt][nt][q] = 0.f;

#pragma unroll
    for (int ch = 0; ch < 4; ch++) {
        const uint32_t aBase = sb + H1OFF + ch * 8192;
        const uint32_t bBase = sb + Q2OFF + ch * 16384;
#pragma unroll
        for (int ks = 0; ks < 4; ks++) {
            const int kbA = ks * 32 + 16 * halfA;
            const int kbB = ks * 32 + 16 * halfB;
            uint32_t a[2][4], bfr[4][2];
#pragma unroll
            for (int mt = 0; mt < 2; mt++)
                ldsm4(a[mt], aBase + pA[mt] + (kbA ^ xA[mt]));
#pragma unroll
            for (int nt = 0; nt < 4; nt++)
                ldsm2(bfr[nt], bBase + (wn * 32 + nt * 8 + l8) * 128 + (kbB ^ xB));
#pragma unroll
            for (int mt = 0; mt < 2; mt++)
#pragma unroll
                for (int nt = 0; nt < 4; nt++)
                    mma16816(acc2[mt][nt], a[mt], bfr[nt]);
        }
    }

    // --- G3 epilogue: +bq2 -> H2pre fp32 [0, 34K) ---
#pragma unroll
    for (int nt = 0; nt < 4; nt++) {
        const int c = wn * 32 + nt * 8 + qd * 2;
        const float b0 = bq2[c], b1 = bq2[c + 1];
#pragma unroll
        for (int mt = 0; mt < 2; mt++) {
            const int r0 = wm * 32 + mt * 16 + gid;
#pragma unroll
            for (int half = 0; half < 2; half++) {
                const int row = r0 + 8 * half;
                float2 o;
                o.x = acc2[mt][nt][2 * half + 0] + b0;
                o.y = acc2[mt][nt][2 * half + 1] + b1;
                *(float2*)(sm + row * PRE2_STRIDE + c * 4) = o;
            }
        }
    }
    __syncthreads();

    // --- LN2 + ReLU + dot(Wq3) -> out ---
    const float bq3v = bq3[0];
#pragma unroll
    for (int j = 0; j < 8; j++) {
        const int row = wid * 8 + j;
        float v[4];
        float s = 0.f;
#pragma unroll
        for (int i = 0; i < 4; i++) {
            v[i] = *(const float*)(sm + row * PRE2_STRIDE + (lane + 32 * i) * 4);
            s += v[i];
        }
#pragma unroll
        for (int o = 16; o; o >>= 1) s += __shfl_xor_sync(0xffffffffu, s, o);
        const float mu = s * (1.0f / 128.0f);
        float vs = 0.f;
#pragma unroll
        for (int i = 0; i < 4; i++) { float d = v[i] - mu; vs += d * d; }
#pragma unroll
        for (int o = 16; o; o >>= 1) vs += __shfl_xor_sync(0xffffffffu, vs, o);
        const float inv = rsqrtf(vs * (1.0f / 128.0f) + 1e-5f);
        float dot = 0.f;
#pragma unroll
        for (int i = 0; i < 4; i++) {
            const int c = lane + 32 * i;
            float y = (v[i] - mu) * inv * ln2g[c] + ln2b[c];
            y = fmaxf(y, 0.f);
            dot = fmaf(y, wq3[c], dot);
        }
#pragma unroll
        for (int o = 16; o; o >>= 1) dot += __shfl_xor_sync(0xffffffffu, dot, o);
        if (lane == 0) out[bm + row] = dot + bq3v;
    }
}

// ---------------- launch ----------------------------------------------------
extern "C" void kernel_launch(void* const* d_in, const int* in_sizes, int n_in,
                              void* d_out, int out_size) {
    const float* state = (const float*)d_in[0];
    const float* action = (const float*)d_in[1];
    const float* W1 = (const float*)d_in[2];
    const float* b1 = (const float*)d_in[3];
    const float* g1 = (const float*)d_in[4];
    const float* W2 = (const float*)d_in[5];
    const float* b2 = (const float*)d_in[6];
    const float* g2 = (const float*)d_in[7];
    const float* Wq1 = (const float*)d_in[8];
    const float* bq1 = (const float*)d_in[9];
    const float* ln1g = (const float*)d_in[10];
    const float* ln1b = (const float*)d_in[11];
    const float* Wq2 = (const float*)d_in[12];
    const float* bq2 = (const float*)d_in[13];
    const float* ln2g = (const float*)d_in[14];
    const float* ln2b = (const float*)d_in[15];
    const float* Wq3 = (const float*)d_in[16];
    const float* bq3 = (const float*)d_in[17];
    float* out = (float*)d_out;

    const int M = in_sizes[0] / 24;
    if (M <= 0) return;

    fp16 *saf, *w1t, *w2t, *q1t, *q2t, *x1f, *x2f;
    float* gt;
    cudaGetSymbolAddress((void**)&saf, g_SAf);
    cudaGetSymbolAddress((void**)&w1t, g_W1t);
    cudaGetSymbolAddress((void**)&w2t, g_W2t);
    cudaGetSymbolAddress((void**)&q1t, g_Q1t);
    cudaGetSymbolAddress((void**)&q2t, g_Q2t);
    cudaGetSymbolAddress((void**)&x1f, g_X1f);
    cudaGetSymbolAddress((void**)&x2f, g_X2f);
    cudaGetSymbolAddress((void**)&gt, g_GATE);

    const int SMEM_G = 2 * (2 * 128 * 64 * 2) + 1024;   // 66560
    const int SMEM_F = 180224 + 1024;                   // 181248
    cudaFuncSetAttribute(mma_gemm, cudaFuncAttributeMaxDynamicSharedMemorySize, SMEM_G);
    cudaFuncSetAttribute(fused_tail, cudaFuncAttributeMaxDynamicSharedMemorySize, SMEM_F);

    prep_saf<<<(M * 64 + 255) / 256, 256>>>(state, action, saf, M);
    prep_w1t<<<(1024 * 64 + 255) / 256, 256>>>(W1, w1t);
    prep_w2t<<<(1024 * 1024 + 255) / 256, 256>>>(W2, w2t);
    prep_wt<<<(256 * 1024 + 255) / 256, 256>>>(Wq1, q1t, 256, 1024);
    prep_wt<<<(128 * 256 + 255) / 256, 256>>>(Wq2, q2t, 128, 256);
    prep_gates<<<1, 64>>>(g1, g2, gt);

    const int MB = M / 128;

    // G0: [M,64pad] @ [1024,64]^T -> X1
    mma_gemm<<<dim3(8, MB), 256, SMEM_G>>>(saf, w1t, 64, 1024, b1, gt, x1f);
    // G1: [M,1024] @ [1024,1024]^T -> X2 (dominant)
    mma_gemm<<<dim3(8, MB), 256, SMEM_G>>>(x1f, w2t, 1024, 1024, b2, gt + 32, x2f);
    // fused: G2 + LN1 + G3 + LN2 + dot
    fused_tail<<<M / 64, 256, SMEM_F>>>(x2f, q1t, q2t,
                                        bq1, ln1g, ln1b,
                                        bq2, ln2g, ln2b,
                                        Wq3, bq3, out);
}